// round 1
// baseline (speedup 1.0000x reference)
#include <cuda_runtime.h>
#include <math.h>

#define EMBED  1024
#define IN_DIM 256
#define HID    256
#define NVIEW  6
#define LAYERS 3
#define BATCH  32
#define MDIM   256
#define ROWS   (BATCH*MDIM*NVIEW)   /* 49152 */
#define BM     (BATCH*MDIM)         /* 8192  */

// ---------------- scratch (device globals; no allocations allowed) ----------
__device__ float g_X1[ROWS*EMBED];      // 192 MB  gelu+residual output
__device__ float g_X2[ROWS*IN_DIM];     //  48 MB  Win projection
__device__ float g_G [ROWS*4*HID];      // 192 MB  per-layer input-proj gates
__device__ float g_Xa[ROWS*HID];        //  48 MB  LSTM layer out (ping)
__device__ float g_Xb[ROWS*HID];        //  48 MB  LSTM layer out (pong)
__device__ float g_HH[BM*4*HID];        //  32 MB  recurrent gate contribution
__device__ float g_h [BM*HID];          //   8 MB
__device__ float g_c [BM*HID];          //   8 MB
__device__ float g_score[BM];

// ---------------- generic NT GEMM: C[M,N] = A[M,K] @ B[N,K]^T + epilogue ----
// 64x64 block tile, 16 K-tile, 256 threads, 4x4 per-thread micro-tile.
__global__ void __launch_bounds__(256)
gemm_nt(const float* __restrict__ A, const float* __restrict__ Bm,
        const float* __restrict__ bias1, const float* __restrict__ bias2,
        const float* __restrict__ resid, int do_gelu,
        float* __restrict__ C, int M, int N, int K)
{
    __shared__ float As[16][65];
    __shared__ float Bs[16][65];

    const int tid = threadIdx.x;
    const int m0  = blockIdx.y * 64;
    const int n0  = blockIdx.x * 64;

    const int lm = tid >> 2;         // 0..63 (row within tile)
    const int lk = (tid & 3) * 4;    // 0,4,8,12

    const float* Aptr = A  + (size_t)(m0 + lm) * K + lk;
    const float* Bptr = Bm + (size_t)(n0 + lm) * K + lk;

    float acc[4][4] = {};

    const int ty4 = (tid >> 4) * 4;  // m offset within tile
    const int tx4 = (tid & 15) * 4;  // n offset within tile

    for (int k0 = 0; k0 < K; k0 += 16) {
        float4 av = *(const float4*)(Aptr + k0);
        float4 bv = *(const float4*)(Bptr + k0);
        As[lk+0][lm] = av.x; As[lk+1][lm] = av.y;
        As[lk+2][lm] = av.z; As[lk+3][lm] = av.w;
        Bs[lk+0][lm] = bv.x; Bs[lk+1][lm] = bv.y;
        Bs[lk+2][lm] = bv.z; Bs[lk+3][lm] = bv.w;
        __syncthreads();

        #pragma unroll
        for (int kk = 0; kk < 16; kk++) {
            float a[4], b[4];
            #pragma unroll
            for (int i = 0; i < 4; i++) { a[i] = As[kk][ty4+i]; b[i] = Bs[kk][tx4+i]; }
            #pragma unroll
            for (int i = 0; i < 4; i++)
                #pragma unroll
                for (int j = 0; j < 4; j++)
                    acc[i][j] = fmaf(a[i], b[j], acc[i][j]);
        }
        __syncthreads();
    }

    #pragma unroll
    for (int i = 0; i < 4; i++) {
        const int m = m0 + ty4 + i;
        #pragma unroll
        for (int j = 0; j < 4; j++) {
            const int n = n0 + tx4 + j;
            float v = acc[i][j];
            if (bias1) v += bias1[n];
            if (bias2) v += bias2[n];
            if (do_gelu) v = 0.5f * v * (1.0f + erff(v * 0.70710678118654752f));
            if (resid)  v += resid[(size_t)m * N + n];
            C[(size_t)m * N + n] = v;
        }
    }
}

// ---------------- LSTM pointwise cell --------------------------------------
__device__ __forceinline__ float sigf(float x) { return 1.0f / (1.0f + expf(-x)); }

__global__ void __launch_bounds__(256)
lstm_cell(const float* __restrict__ G, const float* __restrict__ HH,
          float* __restrict__ h, float* __restrict__ c,
          float* __restrict__ Xout, int t, int useHH)
{
    const int idx = blockIdx.x * blockDim.x + threadIdx.x;  // BM*HID threads
    const int r = idx >> 8;          // batch row (0..8191)
    const int j = idx & 255;         // hidden unit

    const float* g = G + (size_t)(r * NVIEW + t) * (4 * HID);
    float gi = g[j], gf = g[j + HID], gg = g[j + 2*HID], go = g[j + 3*HID];

    float cc = 0.0f;
    if (useHH) {
        const float* hh = HH + (size_t)r * (4 * HID);
        gi += hh[j]; gf += hh[j + HID]; gg += hh[j + 2*HID]; go += hh[j + 3*HID];
        cc = c[idx];
    }
    const float cn = sigf(gf) * cc + sigf(gi) * tanhf(gg);
    const float hn = sigf(go) * tanhf(cn);
    c[idx] = cn;
    h[idx] = hn;
    Xout[(size_t)(r * NVIEW + t) * HID + j] = hn;
}

// ---------------- head: per-(b,m) score ------------------------------------
__global__ void __launch_bounds__(192)
score_kernel(const float* __restrict__ X, const float* __restrict__ Wv,
             const float* __restrict__ bv, const float* __restrict__ Ws,
             const float* __restrict__ bs, float* __restrict__ score)
{
    const int bm   = blockIdx.x;          // 0..8191
    const int w    = threadIdx.x >> 5;    // view index 0..5
    const int lane = threadIdx.x & 31;
    __shared__ float sh[NVIEW];

    const float* x = X + (size_t)(bm * NVIEW + w) * HID;
    float p = 0.0f;
    #pragma unroll
    for (int k = lane; k < HID; k += 32) p += x[k] * Wv[k];
    #pragma unroll
    for (int o = 16; o; o >>= 1) p += __shfl_xor_sync(0xffffffffu, p, o);
    if (lane == 0) sh[w] = (p + bv[0]) * Ws[w];
    __syncthreads();
    if (threadIdx.x == 0) {
        float s = bs[0];
        #pragma unroll
        for (int n = 0; n < NVIEW; n++) s += sh[n];
        score[bm] = s;
    }
}

__global__ void __launch_bounds__(256)
mean_kernel(const float* __restrict__ score, float* __restrict__ out)
{
    const int b = blockIdx.x;
    const int t = threadIdx.x;
    __shared__ float sh[256];
    sh[t] = score[b * MDIM + t];
    __syncthreads();
    for (int o = 128; o; o >>= 1) { if (t < o) sh[t] += sh[t + o]; __syncthreads(); }
    if (t == 0) out[b] = sh[0] * (1.0f / MDIM);
}

// ---------------- launch ----------------------------------------------------
extern "C" void kernel_launch(void* const* d_in, const int* in_sizes, int n_in,
                              void* d_out, int out_size)
{
    const float* b_x_swin = (const float*)d_in[0];
    const float* b_x_conv = (const float*)d_in[1];
    const float* Wc   = (const float*)d_in[2];
    const float* bc   = (const float*)d_in[3];
    const float* Win  = (const float*)d_in[4];
    const float* b_in = (const float*)d_in[5];
    const float* Wih  = (const float*)d_in[6];
    const float* Whh  = (const float*)d_in[7];
    const float* bih  = (const float*)d_in[8];
    const float* bhh  = (const float*)d_in[9];
    const float* Wv   = (const float*)d_in[10];
    const float* bv   = (const float*)d_in[11];
    const float* Ws   = (const float*)d_in[12];
    const float* bs   = (const float*)d_in[13];
    float* out = (float*)d_out;

    float *X1, *X2, *G, *Xa, *Xb, *HH, *h, *c, *score;
    cudaGetSymbolAddress((void**)&X1, g_X1);
    cudaGetSymbolAddress((void**)&X2, g_X2);
    cudaGetSymbolAddress((void**)&G,  g_G);
    cudaGetSymbolAddress((void**)&Xa, g_Xa);
    cudaGetSymbolAddress((void**)&Xb, g_Xb);
    cudaGetSymbolAddress((void**)&HH, g_HH);
    cudaGetSymbolAddress((void**)&h,  g_h);
    cudaGetSymbolAddress((void**)&c,  g_c);
    cudaGetSymbolAddress((void**)&score, g_score);

    // 1) X1 = b_x_swin + gelu(b_x_conv @ Wc^T + bc)     [49152, 1024]
    gemm_nt<<<dim3(EMBED/64, ROWS/64), 256>>>(
        b_x_conv, Wc, bc, nullptr, b_x_swin, 1, X1, ROWS, EMBED, EMBED);

    // 2) X2 = X1 @ Win^T + b_in                         [49152, 256]
    gemm_nt<<<dim3(IN_DIM/64, ROWS/64), 256>>>(
        X1, Win, b_in, nullptr, nullptr, 0, X2, ROWS, IN_DIM, EMBED);

    // 3) LSTM layers
    const float* layer_in[LAYERS] = { X2, Xa, Xb };
    float*       layer_out[LAYERS] = { Xa, Xb, Xa };
    for (int l = 0; l < LAYERS; l++) {
        const float* Wih_l = Wih + (size_t)l * 4 * HID * IN_DIM;
        const float* Whh_l = Whh + (size_t)l * 4 * HID * HID;
        const float* bih_l = bih + (size_t)l * 4 * HID;
        const float* bhh_l = bhh + (size_t)l * 4 * HID;

        // hoisted input projection for all timesteps:
        // G = Xin @ Wih^T + bih + bhh                   [49152, 1024]
        gemm_nt<<<dim3(4*HID/64, ROWS/64), 256>>>(
            layer_in[l], Wih_l, bih_l, bhh_l, nullptr, 0, G, ROWS, 4*HID, IN_DIM);

        // t = 0: h = c = 0 -> no recurrent GEMM
        lstm_cell<<<(BM*HID)/256, 256>>>(G, HH, h, c, layer_out[l], 0, 0);

        for (int t = 1; t < NVIEW; t++) {
            // HH = h @ Whh^T                             [8192, 1024]
            gemm_nt<<<dim3(4*HID/64, BM/64), 256>>>(
                h, Whh_l, nullptr, nullptr, nullptr, 0, HH, BM, 4*HID, HID);
            lstm_cell<<<(BM*HID)/256, 256>>>(G, HH, h, c, layer_out[l], t, 1);
        }
    }

    // 4) head: v = x@Wv^T+bv ; score = v@Ws^T+bs ; out = mean_m(score)
    score_kernel<<<BM, 192>>>(layer_out[LAYERS-1], Wv, bv, Ws, bs, score);
    mean_kernel<<<BATCH, 256>>>(score, out);
}

// round 9
// speedup vs baseline: 2.0731x; 2.0731x over previous
#include <cuda_runtime.h>
#include <mma.h>
#include <math.h>
#include <stdint.h>

using namespace nvcuda;

#define EMBED  1024
#define IN_DIM 256
#define HID    256
#define NVIEW  6
#define LAYERS 3
#define BATCH  32
#define MDIM   256
#define ROWS   (BATCH*MDIM*NVIEW)   /* 49152 */
#define BM     (BATCH*MDIM)         /* 8192  */

// ---------------- scratch (device globals; no allocations allowed) ----------
__device__ float g_X1[ROWS*EMBED];      // 192 MB
__device__ float g_X2[ROWS*IN_DIM];     //  48 MB
__device__ float g_G [ROWS*4*HID];      // 192 MB
__device__ float g_Xa[ROWS*HID];        //  48 MB
__device__ float g_Xb[ROWS*HID];        //  48 MB
__device__ float g_HH[BM*4*HID];        //  32 MB
__device__ float g_h [BM*HID];
__device__ float g_c [BM*HID];
__device__ float g_score[BM];

// ---------------- tf32 WMMA NT GEMM -----------------------------------------
// C[M,N] = A[M,K] @ B[N,K]^T (+ bias(es), gelu, residual)
// 128x128 block tile, 256 threads = 8 warps (4M x 2N), warp tile 32x64.
// K staged by 32 floats; 2-stage cp.async double buffer; smem rows padded to 36.
#define KST     32
#define LDS_PAD 36                       /* floats per smem row */
#define STAGE_FLOATS (128*LDS_PAD)       /* per matrix per stage */
#define SMEM_FLOATS  (4*STAGE_FLOATS)    /* A0,B0,A1,B1 = 73728 B */
#define EPI_LD  132

__device__ __forceinline__ void cpasync16(uint32_t dst, const void* src) {
    asm volatile("cp.async.cg.shared.global [%0], [%1], 16;" :: "r"(dst), "l"(src));
}
__device__ __forceinline__ uint32_t smem_u32(const void* p) {
    uint32_t a;
    asm("{ .reg .u64 t; cvta.to.shared.u64 t, %1; cvt.u32.u64 %0, t; }" : "=r"(a) : "l"(p));
    return a;
}

template<int DO_GELU, int HAS_RES, int NB>
__global__ void __launch_bounds__(256, 2)
gemm_tc(const float* __restrict__ A, const float* __restrict__ Bm,
        const float* __restrict__ bias1, const float* __restrict__ bias2,
        const float* __restrict__ resid,
        float* __restrict__ C, int N, int K)
{
    extern __shared__ float smem[];
    float* As[2] = { smem,                  smem + 2*STAGE_FLOATS };
    float* Bs[2] = { smem + STAGE_FLOATS,   smem + 3*STAGE_FLOATS };

    const int tid = threadIdx.x;
    const int wid = tid >> 5;
    const int wm  = wid & 3;          // warp row (M), 0..3
    const int wn  = wid >> 2;         // warp col (N), 0..1
    const int m0  = blockIdx.y * 128, n0 = blockIdx.x * 128;

    const float* Ab = A  + (size_t)m0 * K;
    const float* Bb = Bm + (size_t)n0 * K;
    const int nst = K / KST;

    wmma::fragment<wmma::accumulator, 16, 16, 8, float> cf[2][4];
    #pragma unroll
    for (int i = 0; i < 2; i++)
        #pragma unroll
        for (int j = 0; j < 4; j++) wmma::fill_fragment(cf[i][j], 0.0f);

    auto load_stage = [&](int s) {
        const int buf = s & 1;
        const uint32_t da = smem_u32(As[buf]), db = smem_u32(Bs[buf]);
        const int k0 = s * KST;
        #pragma unroll
        for (int i = 0; i < 4; i++) {                 // 1024 float4 per matrix
            const int idx = tid + i*256;
            const int row = idx >> 3, c4 = idx & 7;   // 8 float4 per 32-float row
            const uint32_t off = (uint32_t)(row*LDS_PAD + c4*4) * 4u;
            cpasync16(da + off, Ab + (size_t)row*K + k0 + c4*4);
            cpasync16(db + off, Bb + (size_t)row*K + k0 + c4*4);
        }
        asm volatile("cp.async.commit_group;" ::: "memory");
    };

    load_stage(0);
    for (int s = 0; s < nst; s++) {
        if (s + 1 < nst) {
            load_stage(s + 1);
            asm volatile("cp.async.wait_group 1;" ::: "memory");
        } else {
            asm volatile("cp.async.wait_group 0;" ::: "memory");
        }
        __syncthreads();

        const float* Ap = As[s & 1];
        const float* Bp = Bs[s & 1];
        #pragma unroll
        for (int ks = 0; ks < KST/8; ks++) {
            const int kk = ks * 8;
            wmma::fragment<wmma::matrix_a, 16, 16, 8, wmma::precision::tf32, wmma::row_major> af[2];
            wmma::fragment<wmma::matrix_b, 16, 16, 8, wmma::precision::tf32, wmma::col_major> bf[4];
            #pragma unroll
            for (int i = 0; i < 2; i++) {
                wmma::load_matrix_sync(af[i], Ap + (wm*32 + i*16)*LDS_PAD + kk, LDS_PAD);
                #pragma unroll
                for (int e = 0; e < af[i].num_elements; e++)
                    af[i].x[e] = wmma::__float_to_tf32(af[i].x[e]);
            }
            #pragma unroll
            for (int j = 0; j < 4; j++) {
                wmma::load_matrix_sync(bf[j], Bp + (wn*64 + j*16)*LDS_PAD + kk, LDS_PAD);
                #pragma unroll
                for (int e = 0; e < bf[j].num_elements; e++)
                    bf[j].x[e] = wmma::__float_to_tf32(bf[j].x[e]);
            }
            #pragma unroll
            for (int i = 0; i < 2; i++)
                #pragma unroll
                for (int j = 0; j < 4; j++)
                    wmma::mma_sync(cf[i][j], af[i], bf[j], cf[i][j]);
        }
        __syncthreads();
    }

    // epilogue: stage C tile in smem (aliases load buffers), then fused ops
    float* Cs = smem;                       // 128 x EPI_LD floats = 67584 B
    #pragma unroll
    for (int i = 0; i < 2; i++)
        #pragma unroll
        for (int j = 0; j < 4; j++)
            wmma::store_matrix_sync(Cs + (wm*32 + i*16)*EPI_LD + wn*64 + j*16,
                                    cf[i][j], EPI_LD, wmma::mem_row_major);
    __syncthreads();

    const int r    = tid >> 1;              // row 0..127
    const int half = tid & 1;               // 64-col half
    const int m    = m0 + r;
    #pragma unroll
    for (int j4 = 0; j4 < 16; j4++) {
        const int cc = half*64 + j4*4;
        const int n  = n0 + cc;
        float4 v = *(const float4*)(Cs + r*EPI_LD + cc);
        if (NB >= 1) { v.x += bias1[n]; v.y += bias1[n+1]; v.z += bias1[n+2]; v.w += bias1[n+3]; }
        if (NB >= 2) { v.x += bias2[n]; v.y += bias2[n+1]; v.z += bias2[n+2]; v.w += bias2[n+3]; }
        if (DO_GELU) {
            v.x = 0.5f*v.x*(1.0f+erff(v.x*0.70710678118654752f));
            v.y = 0.5f*v.y*(1.0f+erff(v.y*0.70710678118654752f));
            v.z = 0.5f*v.z*(1.0f+erff(v.z*0.70710678118654752f));
            v.w = 0.5f*v.w*(1.0f+erff(v.w*0.70710678118654752f));
        }
        if (HAS_RES) {
            float4 rr = *(const float4*)(resid + (size_t)m*N + n);
            v.x += rr.x; v.y += rr.y; v.z += rr.z; v.w += rr.w;
        }
        *(float4*)(C + (size_t)m*N + n) = v;
    }
}

#define SMEM_SZ (SMEM_FLOATS * 4)

// ---------------- LSTM pointwise cell --------------------------------------
__device__ __forceinline__ float sigf(float x) { return 1.0f / (1.0f + expf(-x)); }

__global__ void __launch_bounds__(256)
lstm_cell(const float* __restrict__ G, const float* __restrict__ HH,
          float* __restrict__ h, float* __restrict__ c,
          float* __restrict__ Xout, int t, int useHH)
{
    const int idx = blockIdx.x * blockDim.x + threadIdx.x;
    const int r = idx >> 8;
    const int j = idx & 255;

    const float* g = G + (size_t)(r * NVIEW + t) * (4 * HID);
    float gi = g[j], gf = g[j + HID], gg = g[j + 2*HID], go = g[j + 3*HID];

    float cc = 0.0f;
    if (useHH) {
        const float* hh = HH + (size_t)r * (4 * HID);
        gi += hh[j]; gf += hh[j + HID]; gg += hh[j + 2*HID]; go += hh[j + 3*HID];
        cc = c[idx];
    }
    const float cn = sigf(gf) * cc + sigf(gi) * tanhf(gg);
    const float hn = sigf(go) * tanhf(cn);
    c[idx] = cn;
    h[idx] = hn;
    Xout[(size_t)(r * NVIEW + t) * HID + j] = hn;
}

// ---------------- head ------------------------------------------------------
__global__ void __launch_bounds__(192)
score_kernel(const float* __restrict__ X, const float* __restrict__ Wv,
             const float* __restrict__ bv, const float* __restrict__ Ws,
             const float* __restrict__ bs, float* __restrict__ score)
{
    const int bm   = blockIdx.x;
    const int w    = threadIdx.x >> 5;
    const int lane = threadIdx.x & 31;
    __shared__ float sh[NVIEW];

    const float* x = X + (size_t)(bm * NVIEW + w) * HID;
    float p = 0.0f;
    #pragma unroll
    for (int k = lane; k < HID; k += 32) p += x[k] * Wv[k];
    #pragma unroll
    for (int o = 16; o; o >>= 1) p += __shfl_xor_sync(0xffffffffu, p, o);
    if (lane == 0) sh[w] = (p + bv[0]) * Ws[w];
    __syncthreads();
    if (threadIdx.x == 0) {
        float s = bs[0];
        #pragma unroll
        for (int n = 0; n < NVIEW; n++) s += sh[n];
        score[bm] = s;
    }
}

__global__ void __launch_bounds__(256)
mean_kernel(const float* __restrict__ score, float* __restrict__ out)
{
    const int b = blockIdx.x;
    const int t = threadIdx.x;
    __shared__ float sh[256];
    sh[t] = score[b * MDIM + t];
    __syncthreads();
    for (int o = 128; o; o >>= 1) { if (t < o) sh[t] += sh[t + o]; __syncthreads(); }
    if (t == 0) out[b] = sh[0] * (1.0f / MDIM);
}

// ---------------- launch ----------------------------------------------------
extern "C" void kernel_launch(void* const* d_in, const int* in_sizes, int n_in,
                              void* d_out, int out_size)
{
    const float* b_x_swin = (const float*)d_in[0];
    const float* b_x_conv = (const float*)d_in[1];
    const float* Wc   = (const float*)d_in[2];
    const float* bc   = (const float*)d_in[3];
    const float* Win  = (const float*)d_in[4];
    const float* b_in = (const float*)d_in[5];
    const float* Wih  = (const float*)d_in[6];
    const float* Whh  = (const float*)d_in[7];
    const float* bih  = (const float*)d_in[8];
    const float* bhh  = (const float*)d_in[9];
    const float* Wv   = (const float*)d_in[10];
    const float* bv   = (const float*)d_in[11];
    const float* Ws   = (const float*)d_in[12];
    const float* bs   = (const float*)d_in[13];
    float* out = (float*)d_out;

    float *X1, *X2, *G, *Xa, *Xb, *HH, *h, *c, *score;
    cudaGetSymbolAddress((void**)&X1, g_X1);
    cudaGetSymbolAddress((void**)&X2, g_X2);
    cudaGetSymbolAddress((void**)&G,  g_G);
    cudaGetSymbolAddress((void**)&Xa, g_Xa);
    cudaGetSymbolAddress((void**)&Xb, g_Xb);
    cudaGetSymbolAddress((void**)&HH, g_HH);
    cudaGetSymbolAddress((void**)&h,  g_h);
    cudaGetSymbolAddress((void**)&c,  g_c);
    cudaGetSymbolAddress((void**)&score, g_score);

    cudaFuncSetAttribute(gemm_tc<1,1,1>, cudaFuncAttributeMaxDynamicSharedMemorySize, SMEM_SZ);
    cudaFuncSetAttribute(gemm_tc<0,0,1>, cudaFuncAttributeMaxDynamicSharedMemorySize, SMEM_SZ);
    cudaFuncSetAttribute(gemm_tc<0,0,2>, cudaFuncAttributeMaxDynamicSharedMemorySize, SMEM_SZ);
    cudaFuncSetAttribute(gemm_tc<0,0,0>, cudaFuncAttributeMaxDynamicSharedMemorySize, SMEM_SZ);

    // 1) X1 = b_x_swin + gelu(b_x_conv @ Wc^T + bc)     [49152, 1024]
    gemm_tc<1,1,1><<<dim3(EMBED/128, ROWS/128), 256, SMEM_SZ>>>(
        b_x_conv, Wc, bc, nullptr, b_x_swin, X1, EMBED, EMBED);

    // 2) X2 = X1 @ Win^T + b_in                         [49152, 256]
    gemm_tc<0,0,1><<<dim3(IN_DIM/128, ROWS/128), 256, SMEM_SZ>>>(
        X1, Win, b_in, nullptr, nullptr, X2, IN_DIM, EMBED);

    // 3) LSTM layers
    const float* layer_in[LAYERS]  = { X2, Xa, Xb };
    float*       layer_out[LAYERS] = { Xa, Xb, Xa };
    for (int l = 0; l < LAYERS; l++) {
        const float* Wih_l = Wih + (size_t)l * 4 * HID * IN_DIM;
        const float* Whh_l = Whh + (size_t)l * 4 * HID * HID;
        const float* bih_l = bih + (size_t)l * 4 * HID;
        const float* bhh_l = bhh + (size_t)l * 4 * HID;

        // G = Xin @ Wih^T + bih + bhh                   [49152, 1024]
        gemm_tc<0,0,2><<<dim3(4*HID/128, ROWS/128), 256, SMEM_SZ>>>(
            layer_in[l], Wih_l, bih_l, bhh_l, nullptr, G, 4*HID, IN_DIM);

        // t = 0: h = c = 0 -> no recurrent GEMM
        lstm_cell<<<(BM*HID)/256, 256>>>(G, HH, h, c, layer_out[l], 0, 0);

        for (int t = 1; t < NVIEW; t++) {
            // HH = h @ Whh^T                             [8192, 1024]
            gemm_tc<0,0,0><<<dim3(4*HID/128, BM/128), 256, SMEM_SZ>>>(
                h, Whh_l, nullptr, nullptr, nullptr, HH, 4*HID, HID);
            lstm_cell<<<(BM*HID)/256, 256>>>(G, HH, h, c, layer_out[l], t, 1);
        }
    }

    // 4) head
    score_kernel<<<BM, 192>>>(layer_out[LAYERS-1], Wv, bv, Ws, bs, score);
    mean_kernel<<<BATCH, 256>>>(score, out);
}

// round 10
// speedup vs baseline: 2.1500x; 1.0371x over previous
#include <cuda_runtime.h>
#include <mma.h>
#include <math.h>
#include <stdint.h>

using namespace nvcuda;

#define EMBED  1024
#define IN_DIM 256
#define HID    256
#define NVIEW  6
#define LAYERS 3
#define BATCH  32
#define MDIM   256
#define ROWS   (BATCH*MDIM*NVIEW)   /* 49152 */
#define BM     (BATCH*MDIM)         /* 8192  */

// ---------------- scratch (device globals; no allocations allowed) ----------
__device__ float g_X1[ROWS*EMBED];      // 192 MB
__device__ float g_X2[ROWS*IN_DIM];     //  48 MB
__device__ float g_G [ROWS*4*HID];      // 192 MB
__device__ float g_Xa[ROWS*HID];        //  48 MB
__device__ float g_Xb[ROWS*HID];        //  48 MB
__device__ float g_h [BM*HID];
__device__ float g_h2[BM*HID];
__device__ float g_c [BM*HID];
__device__ float g_score[BM];

// ---------------- shared GEMM config ----------------------------------------
#define KST     32
#define LDS_PAD 36                       /* floats per smem row */
#define STAGE_FLOATS (128*LDS_PAD)
#define SMEM_FLOATS  (4*STAGE_FLOATS)    /* A0,B0,A1,B1 = 73728 B */
#define EPI_LD  132
#define SMEM_SZ (SMEM_FLOATS * 4)

__device__ __forceinline__ void cpasync16(uint32_t dst, const void* src) {
    asm volatile("cp.async.cg.shared.global [%0], [%1], 16;" :: "r"(dst), "l"(src));
}
__device__ __forceinline__ uint32_t smem_u32(const void* p) {
    uint32_t a;
    asm("{ .reg .u64 t; cvta.to.shared.u64 t, %1; cvt.u32.u64 %0, t; }" : "=r"(a) : "l"(p));
    return a;
}
__device__ __forceinline__ float sigf(float x) { return 1.0f / (1.0f + expf(-x)); }

// ---------------- tf32 WMMA NT GEMM -----------------------------------------
// C[M,N] = A[M,K] @ B[N,K]^T (+ bias(es), gelu, residual)
template<int DO_GELU, int HAS_RES, int NB>
__global__ void __launch_bounds__(256, 2)
gemm_tc(const float* __restrict__ A, const float* __restrict__ Bm,
        const float* __restrict__ bias1, const float* __restrict__ bias2,
        const float* __restrict__ resid,
        float* __restrict__ C, int N, int K)
{
    extern __shared__ float smem[];
    float* As[2] = { smem,                  smem + 2*STAGE_FLOATS };
    float* Bs[2] = { smem + STAGE_FLOATS,   smem + 3*STAGE_FLOATS };

    const int tid = threadIdx.x;
    const int wid = tid >> 5;
    const int wm  = wid & 3;
    const int wn  = wid >> 2;
    const int m0  = blockIdx.y * 128, n0 = blockIdx.x * 128;

    const float* Ab = A  + (size_t)m0 * K;
    const float* Bb = Bm + (size_t)n0 * K;
    const int nst = K / KST;

    wmma::fragment<wmma::accumulator, 16, 16, 8, float> cf[2][4];
    #pragma unroll
    for (int i = 0; i < 2; i++)
        #pragma unroll
        for (int j = 0; j < 4; j++) wmma::fill_fragment(cf[i][j], 0.0f);

    auto load_stage = [&](int s) {
        const int buf = s & 1;
        const uint32_t da = smem_u32(As[buf]), db = smem_u32(Bs[buf]);
        const int k0 = s * KST;
        #pragma unroll
        for (int i = 0; i < 4; i++) {
            const int idx = tid + i*256;
            const int row = idx >> 3, c4 = idx & 7;
            const uint32_t off = (uint32_t)(row*LDS_PAD + c4*4) * 4u;
            cpasync16(da + off, Ab + (size_t)row*K + k0 + c4*4);
            cpasync16(db + off, Bb + (size_t)row*K + k0 + c4*4);
        }
        asm volatile("cp.async.commit_group;" ::: "memory");
    };

    load_stage(0);
    for (int s = 0; s < nst; s++) {
        if (s + 1 < nst) {
            load_stage(s + 1);
            asm volatile("cp.async.wait_group 1;" ::: "memory");
        } else {
            asm volatile("cp.async.wait_group 0;" ::: "memory");
        }
        __syncthreads();

        const float* Ap = As[s & 1];
        const float* Bp = Bs[s & 1];
        #pragma unroll
        for (int ks = 0; ks < KST/8; ks++) {
            const int kk = ks * 8;
            wmma::fragment<wmma::matrix_a, 16, 16, 8, wmma::precision::tf32, wmma::row_major> af[2];
            wmma::fragment<wmma::matrix_b, 16, 16, 8, wmma::precision::tf32, wmma::col_major> bf[4];
            #pragma unroll
            for (int i = 0; i < 2; i++) {
                wmma::load_matrix_sync(af[i], Ap + (wm*32 + i*16)*LDS_PAD + kk, LDS_PAD);
                #pragma unroll
                for (int e = 0; e < af[i].num_elements; e++)
                    af[i].x[e] = wmma::__float_to_tf32(af[i].x[e]);
            }
            #pragma unroll
            for (int j = 0; j < 4; j++) {
                wmma::load_matrix_sync(bf[j], Bp + (wn*64 + j*16)*LDS_PAD + kk, LDS_PAD);
                #pragma unroll
                for (int e = 0; e < bf[j].num_elements; e++)
                    bf[j].x[e] = wmma::__float_to_tf32(bf[j].x[e]);
            }
            #pragma unroll
            for (int i = 0; i < 2; i++)
                #pragma unroll
                for (int j = 0; j < 4; j++)
                    wmma::mma_sync(cf[i][j], af[i], bf[j], cf[i][j]);
        }
        __syncthreads();
    }

    float* Cs = smem;
    #pragma unroll
    for (int i = 0; i < 2; i++)
        #pragma unroll
        for (int j = 0; j < 4; j++)
            wmma::store_matrix_sync(Cs + (wm*32 + i*16)*EPI_LD + wn*64 + j*16,
                                    cf[i][j], EPI_LD, wmma::mem_row_major);
    __syncthreads();

    const int r    = tid >> 1;
    const int half = tid & 1;
    const int m    = m0 + r;
    #pragma unroll
    for (int j4 = 0; j4 < 16; j4++) {
        const int cc = half*64 + j4*4;
        const int n  = n0 + cc;
        float4 v = *(const float4*)(Cs + r*EPI_LD + cc);
        if (NB >= 1) { v.x += bias1[n]; v.y += bias1[n+1]; v.z += bias1[n+2]; v.w += bias1[n+3]; }
        if (NB >= 2) { v.x += bias2[n]; v.y += bias2[n+1]; v.z += bias2[n+2]; v.w += bias2[n+3]; }
        if (DO_GELU) {
            v.x = 0.5f*v.x*(1.0f+erff(v.x*0.70710678118654752f));
            v.y = 0.5f*v.y*(1.0f+erff(v.y*0.70710678118654752f));
            v.z = 0.5f*v.z*(1.0f+erff(v.z*0.70710678118654752f));
            v.w = 0.5f*v.w*(1.0f+erff(v.w*0.70710678118654752f));
        }
        if (HAS_RES) {
            float4 rr = *(const float4*)(resid + (size_t)m*N + n);
            v.x += rr.x; v.y += rr.y; v.z += rr.z; v.w += rr.w;
        }
        *(float4*)(C + (size_t)m*N + n) = v;
    }
}

// ---------------- fused recurrent step: HH GEMM + LSTM cell ------------------
// CTA (jb, rt): rows rt*128..+128, hidden band jb*32..+32, all 4 gates.
// B smem row (g*32+jj) <- Whh row (g*256 + jb*32 + jj). N tile = 128 = 4x32.
// Epilogue: gates = G + HHtile, cell update, write c, h_out, Xout.
__global__ void __launch_bounds__(256, 2)
lstm_step(const float* __restrict__ hin, const float* __restrict__ Whh,
          const float* __restrict__ G, float* __restrict__ hout,
          float* __restrict__ c, float* __restrict__ Xout, int t)
{
    extern __shared__ float smem[];
    float* As[2] = { smem,                  smem + 2*STAGE_FLOATS };
    float* Bs[2] = { smem + STAGE_FLOATS,   smem + 3*STAGE_FLOATS };

    const int tid = threadIdx.x;
    const int wid = tid >> 5;
    const int wm  = wid & 3;
    const int wn  = wid >> 2;
    const int jb  = blockIdx.x;            // 0..7 hidden band
    const int r0  = blockIdx.y * 128;      // row tile
    const int K   = HID;                   // 256
    const int nst = K / KST;               // 8

    wmma::fragment<wmma::accumulator, 16, 16, 8, float> cf[2][4];
    #pragma unroll
    for (int i = 0; i < 2; i++)
        #pragma unroll
        for (int j = 0; j < 4; j++) wmma::fill_fragment(cf[i][j], 0.0f);

    auto load_stage = [&](int s) {
        const int buf = s & 1;
        const uint32_t da = smem_u32(As[buf]), db = smem_u32(Bs[buf]);
        const int k0 = s * KST;
        #pragma unroll
        for (int i = 0; i < 4; i++) {
            const int idx = tid + i*256;
            const int row = idx >> 3, c4 = idx & 7;
            const uint32_t off = (uint32_t)(row*LDS_PAD + c4*4) * 4u;
            cpasync16(da + off, hin + (size_t)(r0 + row)*K + k0 + c4*4);
            const int brow = (row >> 5)*HID + jb*32 + (row & 31);   // Whh row
            cpasync16(db + off, Whh + (size_t)brow*K + k0 + c4*4);
        }
        asm volatile("cp.async.commit_group;" ::: "memory");
    };

    load_stage(0);
    for (int s = 0; s < nst; s++) {
        if (s + 1 < nst) {
            load_stage(s + 1);
            asm volatile("cp.async.wait_group 1;" ::: "memory");
        } else {
            asm volatile("cp.async.wait_group 0;" ::: "memory");
        }
        __syncthreads();

        const float* Ap = As[s & 1];
        const float* Bp = Bs[s & 1];
        #pragma unroll
        for (int ks = 0; ks < KST/8; ks++) {
            const int kk = ks * 8;
            wmma::fragment<wmma::matrix_a, 16, 16, 8, wmma::precision::tf32, wmma::row_major> af[2];
            wmma::fragment<wmma::matrix_b, 16, 16, 8, wmma::precision::tf32, wmma::col_major> bf[4];
            #pragma unroll
            for (int i = 0; i < 2; i++) {
                wmma::load_matrix_sync(af[i], Ap + (wm*32 + i*16)*LDS_PAD + kk, LDS_PAD);
                #pragma unroll
                for (int e = 0; e < af[i].num_elements; e++)
                    af[i].x[e] = wmma::__float_to_tf32(af[i].x[e]);
            }
            #pragma unroll
            for (int j = 0; j < 4; j++) {
                wmma::load_matrix_sync(bf[j], Bp + (wn*64 + j*16)*LDS_PAD + kk, LDS_PAD);
                #pragma unroll
                for (int e = 0; e < bf[j].num_elements; e++)
                    bf[j].x[e] = wmma::__float_to_tf32(bf[j].x[e]);
            }
            #pragma unroll
            for (int i = 0; i < 2; i++)
                #pragma unroll
                for (int j = 0; j < 4; j++)
                    wmma::mma_sync(cf[i][j], af[i], bf[j], cf[i][j]);
        }
        __syncthreads();
    }

    float* Cs = smem;
    #pragma unroll
    for (int i = 0; i < 2; i++)
        #pragma unroll
        for (int j = 0; j < 4; j++)
            wmma::store_matrix_sync(Cs + (wm*32 + i*16)*EPI_LD + wn*64 + j*16,
                                    cf[i][j], EPI_LD, wmma::mem_row_major);
    __syncthreads();

    // cell epilogue: thread -> (row r, 16-wide half of the 32-unit band)
    const int r    = tid >> 1;
    const int half = tid & 1;
    const int bm   = r0 + r;
    const size_t grow = (size_t)(bm*NVIEW + t) * (4*HID);
    #pragma unroll
    for (int q = 0; q < 4; q++) {
        const int jl = half*16 + q*4;          // 0..31 local j
        const int jg = jb*32 + jl;             // global hidden unit
        float4 Gi = *(const float4*)(G + grow + 0*HID + jg);
        float4 Gf = *(const float4*)(G + grow + 1*HID + jg);
        float4 Gg = *(const float4*)(G + grow + 2*HID + jg);
        float4 Go = *(const float4*)(G + grow + 3*HID + jg);
        float4 cc = *(const float4*)(c + (size_t)bm*HID + jg);
        const float* cr = Cs + r*EPI_LD;
        float gi[4] = { Gi.x + cr[0*32+jl], Gi.y + cr[0*32+jl+1], Gi.z + cr[0*32+jl+2], Gi.w + cr[0*32+jl+3] };
        float gf[4] = { Gf.x + cr[1*32+jl], Gf.y + cr[1*32+jl+1], Gf.z + cr[1*32+jl+2], Gf.w + cr[1*32+jl+3] };
        float gg[4] = { Gg.x + cr[2*32+jl], Gg.y + cr[2*32+jl+1], Gg.z + cr[2*32+jl+2], Gg.w + cr[2*32+jl+3] };
        float go[4] = { Go.x + cr[3*32+jl], Go.y + cr[3*32+jl+1], Go.z + cr[3*32+jl+2], Go.w + cr[3*32+jl+3] };
        float cold[4] = { cc.x, cc.y, cc.z, cc.w };
        float4 cn, hn;
        float* cnp = &cn.x; float* hnp = &hn.x;
        #pragma unroll
        for (int e = 0; e < 4; e++) {
            const float cv = sigf(gf[e]) * cold[e] + sigf(gi[e]) * tanhf(gg[e]);
            cnp[e] = cv;
            hnp[e] = sigf(go[e]) * tanhf(cv);
        }
        *(float4*)(c + (size_t)bm*HID + jg) = cn;
        *(float4*)(hout + (size_t)bm*HID + jg) = hn;
        *(float4*)(Xout + (size_t)(bm*NVIEW + t)*HID + jg) = hn;
    }
}

// ---------------- LSTM pointwise cell (t=0 only: h=c=0) ---------------------
__global__ void __launch_bounds__(256)
lstm_cell0(const float* __restrict__ G, float* __restrict__ h,
           float* __restrict__ c, float* __restrict__ Xout)
{
    const int idx = blockIdx.x * blockDim.x + threadIdx.x;
    const int r = idx >> 8;
    const int j = idx & 255;

    const float* g = G + (size_t)(r * NVIEW) * (4 * HID);
    const float gi = g[j], gf2 = g[j + HID], gg = g[j + 2*HID], go = g[j + 3*HID];
    (void)gf2;
    const float cn = sigf(gi) * tanhf(gg);
    const float hn = sigf(go) * tanhf(cn);
    c[idx] = cn;
    h[idx] = hn;
    Xout[(size_t)(r * NVIEW) * HID + j] = hn;
}

// ---------------- head ------------------------------------------------------
__global__ void __launch_bounds__(192)
score_kernel(const float* __restrict__ X, const float* __restrict__ Wv,
             const float* __restrict__ bv, const float* __restrict__ Ws,
             const float* __restrict__ bs, float* __restrict__ score)
{
    const int bm   = blockIdx.x;
    const int w    = threadIdx.x >> 5;
    const int lane = threadIdx.x & 31;
    __shared__ float sh[NVIEW];

    const float* x = X + (size_t)(bm * NVIEW + w) * HID;
    float p = 0.0f;
    #pragma unroll
    for (int k = lane; k < HID; k += 32) p += x[k] * Wv[k];
    #pragma unroll
    for (int o = 16; o; o >>= 1) p += __shfl_xor_sync(0xffffffffu, p, o);
    if (lane == 0) sh[w] = (p + bv[0]) * Ws[w];
    __syncthreads();
    if (threadIdx.x == 0) {
        float s = bs[0];
        #pragma unroll
        for (int n = 0; n < NVIEW; n++) s += sh[n];
        score[bm] = s;
    }
}

__global__ void __launch_bounds__(256)
mean_kernel(const float* __restrict__ score, float* __restrict__ out)
{
    const int b = blockIdx.x;
    const int t = threadIdx.x;
    __shared__ float sh[256];
    sh[t] = score[b * MDIM + t];
    __syncthreads();
    for (int o = 128; o; o >>= 1) { if (t < o) sh[t] += sh[t + o]; __syncthreads(); }
    if (t == 0) out[b] = sh[0] * (1.0f / MDIM);
}

// ---------------- launch ----------------------------------------------------
extern "C" void kernel_launch(void* const* d_in, const int* in_sizes, int n_in,
                              void* d_out, int out_size)
{
    const float* b_x_swin = (const float*)d_in[0];
    const float* b_x_conv = (const float*)d_in[1];
    const float* Wc   = (const float*)d_in[2];
    const float* bc   = (const float*)d_in[3];
    const float* Win  = (const float*)d_in[4];
    const float* b_in = (const float*)d_in[5];
    const float* Wih  = (const float*)d_in[6];
    const float* Whh  = (const float*)d_in[7];
    const float* bih  = (const float*)d_in[8];
    const float* bhh  = (const float*)d_in[9];
    const float* Wv   = (const float*)d_in[10];
    const float* bv   = (const float*)d_in[11];
    const float* Ws   = (const float*)d_in[12];
    const float* bs   = (const float*)d_in[13];
    float* out = (float*)d_out;

    float *X1, *X2, *G, *Xa, *Xb, *h, *h2, *c, *score;
    cudaGetSymbolAddress((void**)&X1, g_X1);
    cudaGetSymbolAddress((void**)&X2, g_X2);
    cudaGetSymbolAddress((void**)&G,  g_G);
    cudaGetSymbolAddress((void**)&Xa, g_Xa);
    cudaGetSymbolAddress((void**)&Xb, g_Xb);
    cudaGetSymbolAddress((void**)&h,  g_h);
    cudaGetSymbolAddress((void**)&h2, g_h2);
    cudaGetSymbolAddress((void**)&c,  g_c);
    cudaGetSymbolAddress((void**)&score, g_score);

    cudaFuncSetAttribute(gemm_tc<1,1,1>, cudaFuncAttributeMaxDynamicSharedMemorySize, SMEM_SZ);
    cudaFuncSetAttribute(gemm_tc<0,0,1>, cudaFuncAttributeMaxDynamicSharedMemorySize, SMEM_SZ);
    cudaFuncSetAttribute(gemm_tc<0,0,2>, cudaFuncAttributeMaxDynamicSharedMemorySize, SMEM_SZ);
    cudaFuncSetAttribute(lstm_step,      cudaFuncAttributeMaxDynamicSharedMemorySize, SMEM_SZ);

    // 1) X1 = b_x_swin + gelu(b_x_conv @ Wc^T + bc)     [49152, 1024]
    gemm_tc<1,1,1><<<dim3(EMBED/128, ROWS/128), 256, SMEM_SZ>>>(
        b_x_conv, Wc, bc, nullptr, b_x_swin, X1, EMBED, EMBED);

    // 2) X2 = X1 @ Win^T + b_in                         [49152, 256]
    gemm_tc<0,0,1><<<dim3(IN_DIM/128, ROWS/128), 256, SMEM_SZ>>>(
        X1, Win, b_in, nullptr, nullptr, X2, IN_DIM, EMBED);

    // 3) LSTM layers
    const float* layer_in[LAYERS]  = { X2, Xa, Xb };
    float*       layer_out[LAYERS] = { Xa, Xb, Xa };
    float* hp[2] = { h, h2 };
    for (int l = 0; l < LAYERS; l++) {
        const float* Wih_l = Wih + (size_t)l * 4 * HID * IN_DIM;
        const float* Whh_l = Whh + (size_t)l * 4 * HID * HID;
        const float* bih_l = bih + (size_t)l * 4 * HID;
        const float* bhh_l = bhh + (size_t)l * 4 * HID;

        // G = Xin @ Wih^T + bih + bhh                   [49152, 1024]
        gemm_tc<0,0,2><<<dim3(4*HID/128, ROWS/128), 256, SMEM_SZ>>>(
            layer_in[l], Wih_l, bih_l, bhh_l, nullptr, G, 4*HID, IN_DIM);

        // t = 0: h = c = 0 -> pointwise only, writes hp[0]
        lstm_cell0<<<(BM*HID)/256, 256>>>(G, hp[0], c, layer_out[l]);

        // t = 1..5: fused GEMM + cell, ping-pong h
        for (int t = 1; t < NVIEW; t++) {
            lstm_step<<<dim3(HID/32, BM/128), 256, SMEM_SZ>>>(
                hp[(t-1) & 1], Whh_l, G, hp[t & 1], c, layer_out[l], t);
        }
    }

    // 4) head
    score_kernel<<<BM, 192>>>(layer_out[LAYERS-1], Wv, bv, Ws, bs, score);
    mean_kernel<<<BATCH, 256>>>(score, out);
}

// round 11
// speedup vs baseline: 2.2435x; 1.0435x over previous
#include <cuda_runtime.h>
#include <mma.h>
#include <math.h>
#include <stdint.h>

using namespace nvcuda;

#define EMBED  1024
#define IN_DIM 256
#define HID    256
#define NVIEW  6
#define LAYERS 3
#define BATCH  32
#define MDIM   256
#define ROWS   (BATCH*MDIM*NVIEW)   /* 49152 */
#define BM     (BATCH*MDIM)         /* 8192  */

// ---------------- scratch (device globals; no allocations allowed) ----------
__device__ float g_X1[ROWS*EMBED];      // 192 MB
__device__ float g_X2[ROWS*IN_DIM];     //  48 MB
__device__ float g_G [ROWS*4*HID];      // 192 MB
__device__ float g_Xa[ROWS*HID];        //  48 MB
__device__ float g_Xb[ROWS*HID];        //  48 MB
__device__ float g_h [BM*HID];
__device__ float g_h2[BM*HID];
__device__ float g_c [BM*HID];
__device__ float g_score[BM];

// ---------------- shared GEMM config ----------------------------------------
#define KST     32
#define LDS_PAD 36                       /* floats per smem row */
#define STAGE_FLOATS (128*LDS_PAD)
#define SMEM_FLOATS  (4*STAGE_FLOATS)    /* A0,B0,A1,B1 = 73728 B */
#define EPI_LD  132
#define SMEM_SZ (SMEM_FLOATS * 4)

__device__ __forceinline__ void cpasync16(uint32_t dst, const void* src) {
    asm volatile("cp.async.cg.shared.global [%0], [%1], 16;" :: "r"(dst), "l"(src));
}
__device__ __forceinline__ uint32_t smem_u32(const void* p) {
    uint32_t a;
    asm("{ .reg .u64 t; cvta.to.shared.u64 t, %1; cvt.u32.u64 %0, t; }" : "=r"(a) : "l"(p));
    return a;
}
__device__ __forceinline__ float sigf(float x) { return 1.0f / (1.0f + expf(-x)); }

// ---------------- tf32 WMMA NT GEMM -----------------------------------------
// C[M,N] = A[M,K] @ B[N,K]^T (+ bias(es), gelu, residual)
// NOTE: no __float_to_tf32 — HMMA.TF32 reads only the tf32 bit-field, so raw
// fp32 bits give truncation-rounding on inputs (rel_err budget is huge).
template<int DO_GELU, int HAS_RES, int NB>
__global__ void __launch_bounds__(256, 2)
gemm_tc(const float* __restrict__ A, const float* __restrict__ Bm,
        const float* __restrict__ bias1, const float* __restrict__ bias2,
        const float* __restrict__ resid,
        float* __restrict__ C, int N, int K)
{
    extern __shared__ float smem[];
    float* As[2] = { smem,                  smem + 2*STAGE_FLOATS };
    float* Bs[2] = { smem + STAGE_FLOATS,   smem + 3*STAGE_FLOATS };

    const int tid = threadIdx.x;
    const int wid = tid >> 5;
    const int wm  = wid & 3;
    const int wn  = wid >> 2;
    const int m0  = blockIdx.y * 128, n0 = blockIdx.x * 128;

    const float* Ab = A  + (size_t)m0 * K;
    const float* Bb = Bm + (size_t)n0 * K;
    const int nst = K / KST;

    wmma::fragment<wmma::accumulator, 16, 16, 8, float> cf[2][4];
    #pragma unroll
    for (int i = 0; i < 2; i++)
        #pragma unroll
        for (int j = 0; j < 4; j++) wmma::fill_fragment(cf[i][j], 0.0f);

    auto load_stage = [&](int s) {
        const int buf = s & 1;
        const uint32_t da = smem_u32(As[buf]), db = smem_u32(Bs[buf]);
        const int k0 = s * KST;
        #pragma unroll
        for (int i = 0; i < 4; i++) {
            const int idx = tid + i*256;
            const int row = idx >> 3, c4 = idx & 7;
            const uint32_t off = (uint32_t)(row*LDS_PAD + c4*4) * 4u;
            cpasync16(da + off, Ab + (size_t)row*K + k0 + c4*4);
            cpasync16(db + off, Bb + (size_t)row*K + k0 + c4*4);
        }
        asm volatile("cp.async.commit_group;" ::: "memory");
    };

    load_stage(0);
    for (int s = 0; s < nst; s++) {
        if (s + 1 < nst) {
            load_stage(s + 1);
            asm volatile("cp.async.wait_group 1;" ::: "memory");
        } else {
            asm volatile("cp.async.wait_group 0;" ::: "memory");
        }
        __syncthreads();

        const float* Ap = As[s & 1];
        const float* Bp = Bs[s & 1];
        #pragma unroll
        for (int ks = 0; ks < KST/8; ks++) {
            const int kk = ks * 8;
            wmma::fragment<wmma::matrix_a, 16, 16, 8, wmma::precision::tf32, wmma::row_major> af[2];
            wmma::fragment<wmma::matrix_b, 16, 16, 8, wmma::precision::tf32, wmma::col_major> bf[4];
            #pragma unroll
            for (int i = 0; i < 2; i++)
                wmma::load_matrix_sync(af[i], Ap + (wm*32 + i*16)*LDS_PAD + kk, LDS_PAD);
            #pragma unroll
            for (int j = 0; j < 4; j++)
                wmma::load_matrix_sync(bf[j], Bp + (wn*64 + j*16)*LDS_PAD + kk, LDS_PAD);
            #pragma unroll
            for (int i = 0; i < 2; i++)
                #pragma unroll
                for (int j = 0; j < 4; j++)
                    wmma::mma_sync(cf[i][j], af[i], bf[j], cf[i][j]);
        }
        __syncthreads();
    }

    float* Cs = smem;
    #pragma unroll
    for (int i = 0; i < 2; i++)
        #pragma unroll
        for (int j = 0; j < 4; j++)
            wmma::store_matrix_sync(Cs + (wm*32 + i*16)*EPI_LD + wn*64 + j*16,
                                    cf[i][j], EPI_LD, wmma::mem_row_major);
    __syncthreads();

    const int r    = tid >> 1;
    const int half = tid & 1;
    const int m    = m0 + r;
    #pragma unroll
    for (int j4 = 0; j4 < 16; j4++) {
        const int cc = half*64 + j4*4;
        const int n  = n0 + cc;
        float4 v = *(const float4*)(Cs + r*EPI_LD + cc);
        if (NB >= 1) { v.x += bias1[n]; v.y += bias1[n+1]; v.z += bias1[n+2]; v.w += bias1[n+3]; }
        if (NB >= 2) { v.x += bias2[n]; v.y += bias2[n+1]; v.z += bias2[n+2]; v.w += bias2[n+3]; }
        if (DO_GELU) {
            v.x = 0.5f*v.x*(1.0f+erff(v.x*0.70710678118654752f));
            v.y = 0.5f*v.y*(1.0f+erff(v.y*0.70710678118654752f));
            v.z = 0.5f*v.z*(1.0f+erff(v.z*0.70710678118654752f));
            v.w = 0.5f*v.w*(1.0f+erff(v.w*0.70710678118654752f));
        }
        if (HAS_RES) {
            float4 rr = *(const float4*)(resid + (size_t)m*N + n);
            v.x += rr.x; v.y += rr.y; v.z += rr.z; v.w += rr.w;
        }
        *(float4*)(C + (size_t)m*N + n) = v;
    }
}

// ---------------- fused recurrent step: HH GEMM + LSTM cell ------------------
__global__ void __launch_bounds__(256, 2)
lstm_step(const float* __restrict__ hin, const float* __restrict__ Whh,
          const float* __restrict__ G, float* __restrict__ hout,
          float* __restrict__ c, float* __restrict__ Xout, int t)
{
    extern __shared__ float smem[];
    float* As[2] = { smem,                  smem + 2*STAGE_FLOATS };
    float* Bs[2] = { smem + STAGE_FLOATS,   smem + 3*STAGE_FLOATS };

    const int tid = threadIdx.x;
    const int wid = tid >> 5;
    const int wm  = wid & 3;
    const int wn  = wid >> 2;
    const int jb  = blockIdx.x;            // 0..7 hidden band
    const int r0  = blockIdx.y * 128;      // row tile
    const int K   = HID;                   // 256
    const int nst = K / KST;               // 8

    wmma::fragment<wmma::accumulator, 16, 16, 8, float> cf[2][4];
    #pragma unroll
    for (int i = 0; i < 2; i++)
        #pragma unroll
        for (int j = 0; j < 4; j++) wmma::fill_fragment(cf[i][j], 0.0f);

    auto load_stage = [&](int s) {
        const int buf = s & 1;
        const uint32_t da = smem_u32(As[buf]), db = smem_u32(Bs[buf]);
        const int k0 = s * KST;
        #pragma unroll
        for (int i = 0; i < 4; i++) {
            const int idx = tid + i*256;
            const int row = idx >> 3, c4 = idx & 7;
            const uint32_t off = (uint32_t)(row*LDS_PAD + c4*4) * 4u;
            cpasync16(da + off, hin + (size_t)(r0 + row)*K + k0 + c4*4);
            const int brow = (row >> 5)*HID + jb*32 + (row & 31);   // Whh row
            cpasync16(db + off, Whh + (size_t)brow*K + k0 + c4*4);
        }
        asm volatile("cp.async.commit_group;" ::: "memory");
    };

    load_stage(0);
    for (int s = 0; s < nst; s++) {
        if (s + 1 < nst) {
            load_stage(s + 1);
            asm volatile("cp.async.wait_group 1;" ::: "memory");
        } else {
            asm volatile("cp.async.wait_group 0;" ::: "memory");
        }
        __syncthreads();

        const float* Ap = As[s & 1];
        const float* Bp = Bs[s & 1];
        #pragma unroll
        for (int ks = 0; ks < KST/8; ks++) {
            const int kk = ks * 8;
            wmma::fragment<wmma::matrix_a, 16, 16, 8, wmma::precision::tf32, wmma::row_major> af[2];
            wmma::fragment<wmma::matrix_b, 16, 16, 8, wmma::precision::tf32, wmma::col_major> bf[4];
            #pragma unroll
            for (int i = 0; i < 2; i++)
                wmma::load_matrix_sync(af[i], Ap + (wm*32 + i*16)*LDS_PAD + kk, LDS_PAD);
            #pragma unroll
            for (int j = 0; j < 4; j++)
                wmma::load_matrix_sync(bf[j], Bp + (wn*64 + j*16)*LDS_PAD + kk, LDS_PAD);
            #pragma unroll
            for (int i = 0; i < 2; i++)
                #pragma unroll
                for (int j = 0; j < 4; j++)
                    wmma::mma_sync(cf[i][j], af[i], bf[j], cf[i][j]);
        }
        __syncthreads();
    }

    float* Cs = smem;
    #pragma unroll
    for (int i = 0; i < 2; i++)
        #pragma unroll
        for (int j = 0; j < 4; j++)
            wmma::store_matrix_sync(Cs + (wm*32 + i*16)*EPI_LD + wn*64 + j*16,
                                    cf[i][j], EPI_LD, wmma::mem_row_major);
    __syncthreads();

    // cell epilogue: thread -> (row r, 16-wide half of the 32-unit band)
    const int r    = tid >> 1;
    const int half = tid & 1;
    const int bm   = r0 + r;
    const size_t grow = (size_t)(bm*NVIEW + t) * (4*HID);
    #pragma unroll
    for (int q = 0; q < 4; q++) {
        const int jl = half*16 + q*4;          // 0..31 local j
        const int jg = jb*32 + jl;             // global hidden unit
        float4 Gi = *(const float4*)(G + grow + 0*HID + jg);
        float4 Gf = *(const float4*)(G + grow + 1*HID + jg);
        float4 Gg = *(const float4*)(G + grow + 2*HID + jg);
        float4 Go = *(const float4*)(G + grow + 3*HID + jg);
        float4 cc = *(const float4*)(c + (size_t)bm*HID + jg);
        const float* cr = Cs + r*EPI_LD;
        float gi[4] = { Gi.x + cr[0*32+jl], Gi.y + cr[0*32+jl+1], Gi.z + cr[0*32+jl+2], Gi.w + cr[0*32+jl+3] };
        float gf[4] = { Gf.x + cr[1*32+jl], Gf.y + cr[1*32+jl+1], Gf.z + cr[1*32+jl+2], Gf.w + cr[1*32+jl+3] };
        float gg[4] = { Gg.x + cr[2*32+jl], Gg.y + cr[2*32+jl+1], Gg.z + cr[2*32+jl+2], Gg.w + cr[2*32+jl+3] };
        float go[4] = { Go.x + cr[3*32+jl], Go.y + cr[3*32+jl+1], Go.z + cr[3*32+jl+2], Go.w + cr[3*32+jl+3] };
        float cold[4] = { cc.x, cc.y, cc.z, cc.w };
        float4 cn, hn;
        float* cnp = &cn.x; float* hnp = &hn.x;
        #pragma unroll
        for (int e = 0; e < 4; e++) {
            const float cv = sigf(gf[e]) * cold[e] + sigf(gi[e]) * tanhf(gg[e]);
            cnp[e] = cv;
            hnp[e] = sigf(go[e]) * tanhf(cv);
        }
        *(float4*)(c + (size_t)bm*HID + jg) = cn;
        *(float4*)(hout + (size_t)bm*HID + jg) = hn;
        *(float4*)(Xout + (size_t)(bm*NVIEW + t)*HID + jg) = hn;
    }
}

// ---------------- LSTM pointwise cell (t=0 only: h=c=0) ---------------------
__global__ void __launch_bounds__(256)
lstm_cell0(const float* __restrict__ G, float* __restrict__ h,
           float* __restrict__ c, float* __restrict__ Xout)
{
    const int idx = blockIdx.x * blockDim.x + threadIdx.x;
    const int r = idx >> 8;
    const int j = idx & 255;

    const float* g = G + (size_t)(r * NVIEW) * (4 * HID);
    const float gi = g[j], gg = g[j + 2*HID], go = g[j + 3*HID];
    const float cn = sigf(gi) * tanhf(gg);
    const float hn = sigf(go) * tanhf(cn);
    c[idx] = cn;
    h[idx] = hn;
    Xout[(size_t)(r * NVIEW) * HID + j] = hn;
}

// ---------------- head ------------------------------------------------------
__global__ void __launch_bounds__(192)
score_kernel(const float* __restrict__ X, const float* __restrict__ Wv,
             const float* __restrict__ bv, const float* __restrict__ Ws,
             const float* __restrict__ bs, float* __restrict__ score)
{
    const int bm   = blockIdx.x;
    const int w    = threadIdx.x >> 5;
    const int lane = threadIdx.x & 31;
    __shared__ float sh[NVIEW];

    const float* x = X + (size_t)(bm * NVIEW + w) * HID;
    float p = 0.0f;
    #pragma unroll
    for (int k = lane; k < HID; k += 32) p += x[k] * Wv[k];
    #pragma unroll
    for (int o = 16; o; o >>= 1) p += __shfl_xor_sync(0xffffffffu, p, o);
    if (lane == 0) sh[w] = (p + bv[0]) * Ws[w];
    __syncthreads();
    if (threadIdx.x == 0) {
        float s = bs[0];
        #pragma unroll
        for (int n = 0; n < NVIEW; n++) s += sh[n];
        score[bm] = s;
    }
}

__global__ void __launch_bounds__(256)
mean_kernel(const float* __restrict__ score, float* __restrict__ out)
{
    const int b = blockIdx.x;
    const int t = threadIdx.x;
    __shared__ float sh[256];
    sh[t] = score[b * MDIM + t];
    __syncthreads();
    for (int o = 128; o; o >>= 1) { if (t < o) sh[t] += sh[t + o]; __syncthreads(); }
    if (t == 0) out[b] = sh[0] * (1.0f / MDIM);
}

// ---------------- launch ----------------------------------------------------
extern "C" void kernel_launch(void* const* d_in, const int* in_sizes, int n_in,
                              void* d_out, int out_size)
{
    const float* b_x_swin = (const float*)d_in[0];
    const float* b_x_conv = (const float*)d_in[1];
    const float* Wc   = (const float*)d_in[2];
    const float* bc   = (const float*)d_in[3];
    const float* Win  = (const float*)d_in[4];
    const float* b_in = (const float*)d_in[5];
    const float* Wih  = (const float*)d_in[6];
    const float* Whh  = (const float*)d_in[7];
    const float* bih  = (const float*)d_in[8];
    const float* bhh  = (const float*)d_in[9];
    const float* Wv   = (const float*)d_in[10];
    const float* bv   = (const float*)d_in[11];
    const float* Ws   = (const float*)d_in[12];
    const float* bs   = (const float*)d_in[13];
    float* out = (float*)d_out;

    float *X1, *X2, *G, *Xa, *Xb, *h, *h2, *c, *score;
    cudaGetSymbolAddress((void**)&X1, g_X1);
    cudaGetSymbolAddress((void**)&X2, g_X2);
    cudaGetSymbolAddress((void**)&G,  g_G);
    cudaGetSymbolAddress((void**)&Xa, g_Xa);
    cudaGetSymbolAddress((void**)&Xb, g_Xb);
    cudaGetSymbolAddress((void**)&h,  g_h);
    cudaGetSymbolAddress((void**)&h2, g_h2);
    cudaGetSymbolAddress((void**)&c,  g_c);
    cudaGetSymbolAddress((void**)&score, g_score);

    cudaFuncSetAttribute(gemm_tc<1,1,1>, cudaFuncAttributeMaxDynamicSharedMemorySize, SMEM_SZ);
    cudaFuncSetAttribute(gemm_tc<0,0,1>, cudaFuncAttributeMaxDynamicSharedMemorySize, SMEM_SZ);
    cudaFuncSetAttribute(gemm_tc<0,0,2>, cudaFuncAttributeMaxDynamicSharedMemorySize, SMEM_SZ);
    cudaFuncSetAttribute(lstm_step,      cudaFuncAttributeMaxDynamicSharedMemorySize, SMEM_SZ);

    // 1) X1 = b_x_swin + gelu(b_x_conv @ Wc^T + bc)     [49152, 1024]
    gemm_tc<1,1,1><<<dim3(EMBED/128, ROWS/128), 256, SMEM_SZ>>>(
        b_x_conv, Wc, bc, nullptr, b_x_swin, X1, EMBED, EMBED);

    // 2) X2 = X1 @ Win^T + b_in                         [49152, 256]
    gemm_tc<0,0,1><<<dim3(IN_DIM/128, ROWS/128), 256, SMEM_SZ>>>(
        X1, Win, b_in, nullptr, nullptr, X2, IN_DIM, EMBED);

    // 3) LSTM layers
    const float* layer_in[LAYERS]  = { X2, Xa, Xb };
    float*       layer_out[LAYERS] = { Xa, Xb, Xa };
    float* hp[2] = { h, h2 };
    for (int l = 0; l < LAYERS; l++) {
        const float* Wih_l = Wih + (size_t)l * 4 * HID * IN_DIM;
        const float* Whh_l = Whh + (size_t)l * 4 * HID * HID;
        const float* bih_l = bih + (size_t)l * 4 * HID;
        const float* bhh_l = bhh + (size_t)l * 4 * HID;

        // G = Xin @ Wih^T + bih + bhh                   [49152, 1024]
        gemm_tc<0,0,2><<<dim3(4*HID/128, ROWS/128), 256, SMEM_SZ>>>(
            layer_in[l], Wih_l, bih_l, bhh_l, nullptr, G, 4*HID, IN_DIM);

        // t = 0: h = c = 0 -> pointwise only
        lstm_cell0<<<(BM*HID)/256, 256>>>(G, hp[0], c, layer_out[l]);

        // t = 1..5: fused GEMM + cell, ping-pong h
        for (int t = 1; t < NVIEW; t++) {
            lstm_step<<<dim3(HID/32, BM/128), 256, SMEM_SZ>>>(
                hp[(t-1) & 1], Whh_l, G, hp[t & 1], c, layer_out[l], t);
        }
    }

    // 4) head
    score_kernel<<<BM, 192>>>(layer_out[LAYERS-1], Wv, bv, Ws, bs, score);
    mean_kernel<<<BATCH, 256>>>(score, out);
}

// round 13
// speedup vs baseline: 4.9956x; 2.2267x over previous
#include <cuda_runtime.h>
#include <cuda_bf16.h>
#include <mma.h>
#include <math.h>
#include <stdint.h>

using namespace nvcuda;
typedef __nv_bfloat16 bf16;

#define EMBED  1024
#define IN_DIM 256
#define HID    256
#define NVIEW  6
#define LAYERS 3
#define BATCH  32
#define MDIM   256
#define ROWS   (BATCH*MDIM*NVIEW)   /* 49152 */
#define BM     (BATCH*MDIM)         /* 8192  */

// ---------------- scratch (device globals; no allocations allowed) ----------
__device__ bf16  g_bXc[ROWS*EMBED];     //  96 MB  b_x_conv in bf16
__device__ bf16  g_X1 [ROWS*EMBED];     //  96 MB
__device__ bf16  g_X2 [ROWS*IN_DIM];    //  24 MB
__device__ float g_G  [ROWS*4*HID];     // 192 MB  (fp32: gate pre-activations)
__device__ bf16  g_Xa [ROWS*HID];       //  24 MB
__device__ bf16  g_Xb [ROWS*HID];       //  24 MB
__device__ bf16  g_h  [BM*HID];
__device__ bf16  g_h2 [BM*HID];
__device__ float g_c  [BM*HID];
__device__ float g_score[BM];
__device__ bf16  g_bWc [EMBED*EMBED];
__device__ bf16  g_bWin[IN_DIM*EMBED];
__device__ bf16  g_bWih[LAYERS*4*HID*IN_DIM];
__device__ bf16  g_bWhh[LAYERS*4*HID*HID];

// ---------------- shared GEMM config (bf16 operands) -------------------------
#define KSTB    64                        /* K elements per stage */
#define PADB    72                        /* bf16 per smem row (144 B) */
#define STAGE_ELEMS (128*PADB)
#define EPI_LD  132
#define SMEM_SZ (4*STAGE_ELEMS*2)         /* A0,B0,A1,B1 = 73728 B */

__device__ __forceinline__ void cpasync16(uint32_t dst, const void* src) {
    asm volatile("cp.async.cg.shared.global [%0], [%1], 16;" :: "r"(dst), "l"(src));
}
__device__ __forceinline__ uint32_t smem_u32(const void* p) {
    uint32_t a;
    asm("{ .reg .u64 t; cvta.to.shared.u64 t, %1; cvt.u32.u64 %0, t; }" : "=r"(a) : "l"(p));
    return a;
}
__device__ __forceinline__ float sigf(float x) { return 1.0f / (1.0f + expf(-x)); }
__device__ __forceinline__ void store_bf4(bf16* p, float4 v) {
    *(__nv_bfloat162*)(p)     = __floats2bfloat162_rn(v.x, v.y);
    *(__nv_bfloat162*)(p + 2) = __floats2bfloat162_rn(v.z, v.w);
}

// ---------------- fp32 -> bf16 conversion ------------------------------------
__global__ void __launch_bounds__(256)
f2bf(const float* __restrict__ src, bf16* __restrict__ dst, int n)
{
    const int i = (blockIdx.x * blockDim.x + threadIdx.x) * 4;
    if (i < n) {
        float4 v = *(const float4*)(src + i);
        store_bf4(dst + i, v);
    }
}

// ---------------- bf16 WMMA NT GEMM ------------------------------------------
// C[M,N] = A[M,K] @ B[N,K]^T (+ bias(es), gelu, residual); A,B bf16 K-major.
// OUTBF: 1 -> write bf16 C, 0 -> write fp32 C.
template<int DO_GELU, int HAS_RES, int NB, int OUTBF>
__global__ void __launch_bounds__(256, 2)
gemm_bf(const bf16* __restrict__ A, const bf16* __restrict__ Bm,
        const float* __restrict__ bias1, const float* __restrict__ bias2,
        const float* __restrict__ resid,
        void* __restrict__ Cout, int N, int K)
{
    extern __shared__ char smraw[];
    bf16* smem = (bf16*)smraw;
    bf16* As[2] = { smem,                 smem + 2*STAGE_ELEMS };
    bf16* Bs[2] = { smem + STAGE_ELEMS,   smem + 3*STAGE_ELEMS };

    const int tid = threadIdx.x;
    const int wid = tid >> 5;
    const int wm  = wid & 3;
    const int wn  = wid >> 2;
    const int m0  = blockIdx.y * 128, n0 = blockIdx.x * 128;

    const bf16* Ab = A  + (size_t)m0 * K;
    const bf16* Bb = Bm + (size_t)n0 * K;
    const int nst = K / KSTB;

    wmma::fragment<wmma::accumulator, 16, 16, 16, float> cf[2][4];
    #pragma unroll
    for (int i = 0; i < 2; i++)
        #pragma unroll
        for (int j = 0; j < 4; j++) wmma::fill_fragment(cf[i][j], 0.0f);

    auto load_stage = [&](int s) {
        const int buf = s & 1;
        const uint32_t da = smem_u32(As[buf]), db = smem_u32(Bs[buf]);
        const int k0 = s * KSTB;
        #pragma unroll
        for (int i = 0; i < 4; i++) {                  // 1024 16B-chunks per matrix
            const int idx = tid + i*256;
            const int row = idx >> 3, c8 = idx & 7;    // 8 chunks per 64-elt row
            const uint32_t off = (uint32_t)(row*PADB + c8*8) * 2u;
            cpasync16(da + off, Ab + (size_t)row*K + k0 + c8*8);
            cpasync16(db + off, Bb + (size_t)row*K + k0 + c8*8);
        }
        asm volatile("cp.async.commit_group;" ::: "memory");
    };

    load_stage(0);
    for (int s = 0; s < nst; s++) {
        if (s + 1 < nst) {
            load_stage(s + 1);
            asm volatile("cp.async.wait_group 1;" ::: "memory");
        } else {
            asm volatile("cp.async.wait_group 0;" ::: "memory");
        }
        __syncthreads();

        const bf16* Ap = As[s & 1];
        const bf16* Bp = Bs[s & 1];
        #pragma unroll
        for (int ks = 0; ks < KSTB/16; ks++) {
            const int kk = ks * 16;
            wmma::fragment<wmma::matrix_a, 16, 16, 16, bf16, wmma::row_major> af[2];
            wmma::fragment<wmma::matrix_b, 16, 16, 16, bf16, wmma::col_major> bf_[4];
            #pragma unroll
            for (int i = 0; i < 2; i++)
                wmma::load_matrix_sync(af[i], Ap + (wm*32 + i*16)*PADB + kk, PADB);
            #pragma unroll
            for (int j = 0; j < 4; j++)
                wmma::load_matrix_sync(bf_[j], Bp + (wn*64 + j*16)*PADB + kk, PADB);
            #pragma unroll
            for (int i = 0; i < 2; i++)
                #pragma unroll
                for (int j = 0; j < 4; j++)
                    wmma::mma_sync(cf[i][j], af[i], bf_[j], cf[i][j]);
        }
        __syncthreads();
    }

    float* Cs = (float*)smraw;
    #pragma unroll
    for (int i = 0; i < 2; i++)
        #pragma unroll
        for (int j = 0; j < 4; j++)
            wmma::store_matrix_sync(Cs + (wm*32 + i*16)*EPI_LD + wn*64 + j*16,
                                    cf[i][j], EPI_LD, wmma::mem_row_major);
    __syncthreads();

    const int r    = tid >> 1;
    const int half = tid & 1;
    const int m    = m0 + r;
    #pragma unroll
    for (int j4 = 0; j4 < 16; j4++) {
        const int cc = half*64 + j4*4;
        const int n  = n0 + cc;
        float4 v = *(const float4*)(Cs + r*EPI_LD + cc);
        if (NB >= 1) { v.x += bias1[n]; v.y += bias1[n+1]; v.z += bias1[n+2]; v.w += bias1[n+3]; }
        if (NB >= 2) { v.x += bias2[n]; v.y += bias2[n+1]; v.z += bias2[n+2]; v.w += bias2[n+3]; }
        if (DO_GELU) {
            v.x = 0.5f*v.x*(1.0f+erff(v.x*0.70710678118654752f));
            v.y = 0.5f*v.y*(1.0f+erff(v.y*0.70710678118654752f));
            v.z = 0.5f*v.z*(1.0f+erff(v.z*0.70710678118654752f));
            v.w = 0.5f*v.w*(1.0f+erff(v.w*0.70710678118654752f));
        }
        if (HAS_RES) {
            float4 rr = *(const float4*)(resid + (size_t)m*N + n);
            v.x += rr.x; v.y += rr.y; v.z += rr.z; v.w += rr.w;
        }
        if (OUTBF) store_bf4((bf16*)Cout + (size_t)m*N + n, v);
        else       *(float4*)((float*)Cout + (size_t)m*N + n) = v;
    }
}

// ---------------- fused recurrent step: HH GEMM + LSTM cell ------------------
// CTA (jb, rt): rows rt*128..+128, hidden band jb*32..+32, all 4 gates.
__global__ void __launch_bounds__(256, 2)
lstm_step(const bf16* __restrict__ hin, const bf16* __restrict__ Whh,
          const float* __restrict__ G, bf16* __restrict__ hout,
          float* __restrict__ c, bf16* __restrict__ Xout, int t)
{
    extern __shared__ char smraw[];
    bf16* smem = (bf16*)smraw;
    bf16* As[2] = { smem,                 smem + 2*STAGE_ELEMS };
    bf16* Bs[2] = { smem + STAGE_ELEMS,   smem + 3*STAGE_ELEMS };

    const int tid = threadIdx.x;
    const int wid = tid >> 5;
    const int wm  = wid & 3;
    const int wn  = wid >> 2;
    const int jb  = blockIdx.x;
    const int r0  = blockIdx.y * 128;
    const int K   = HID;
    const int nst = K / KSTB;              // 4

    wmma::fragment<wmma::accumulator, 16, 16, 16, float> cf[2][4];
    #pragma unroll
    for (int i = 0; i < 2; i++)
        #pragma unroll
        for (int j = 0; j < 4; j++) wmma::fill_fragment(cf[i][j], 0.0f);

    auto load_stage = [&](int s) {
        const int buf = s & 1;
        const uint32_t da = smem_u32(As[buf]), db = smem_u32(Bs[buf]);
        const int k0 = s * KSTB;
        #pragma unroll
        for (int i = 0; i < 4; i++) {
            const int idx = tid + i*256;
            const int row = idx >> 3, c8 = idx & 7;
            const uint32_t off = (uint32_t)(row*PADB + c8*8) * 2u;
            cpasync16(da + off, hin + (size_t)(r0 + row)*K + k0 + c8*8);
            const int brow = (row >> 5)*HID + jb*32 + (row & 31);   // Whh row
            cpasync16(db + off, Whh + (size_t)brow*K + k0 + c8*8);
        }
        asm volatile("cp.async.commit_group;" ::: "memory");
    };

    load_stage(0);
    for (int s = 0; s < nst; s++) {
        if (s + 1 < nst) {
            load_stage(s + 1);
            asm volatile("cp.async.wait_group 1;" ::: "memory");
        } else {
            asm volatile("cp.async.wait_group 0;" ::: "memory");
        }
        __syncthreads();

        const bf16* Ap = As[s & 1];
        const bf16* Bp = Bs[s & 1];
        #pragma unroll
        for (int ks = 0; ks < KSTB/16; ks++) {
            const int kk = ks * 16;
            wmma::fragment<wmma::matrix_a, 16, 16, 16, bf16, wmma::row_major> af[2];
            wmma::fragment<wmma::matrix_b, 16, 16, 16, bf16, wmma::col_major> bf_[4];
            #pragma unroll
            for (int i = 0; i < 2; i++)
                wmma::load_matrix_sync(af[i], Ap + (wm*32 + i*16)*PADB + kk, PADB);
            #pragma unroll
            for (int j = 0; j < 4; j++)
                wmma::load_matrix_sync(bf_[j], Bp + (wn*64 + j*16)*PADB + kk, PADB);
            #pragma unroll
            for (int i = 0; i < 2; i++)
                #pragma unroll
                for (int j = 0; j < 4; j++)
                    wmma::mma_sync(cf[i][j], af[i], bf_[j], cf[i][j]);
        }
        __syncthreads();
    }

    float* Cs = (float*)smraw;
    #pragma unroll
    for (int i = 0; i < 2; i++)
        #pragma unroll
        for (int j = 0; j < 4; j++)
            wmma::store_matrix_sync(Cs + (wm*32 + i*16)*EPI_LD + wn*64 + j*16,
                                    cf[i][j], EPI_LD, wmma::mem_row_major);
    __syncthreads();

    const int r    = tid >> 1;
    const int half = tid & 1;
    const int bm   = r0 + r;
    const size_t grow = (size_t)(bm*NVIEW + t) * (4*HID);
    #pragma unroll
    for (int q = 0; q < 4; q++) {
        const int jl = half*16 + q*4;
        const int jg = jb*32 + jl;
        float4 Gi = *(const float4*)(G + grow + 0*HID + jg);
        float4 Gf = *(const float4*)(G + grow + 1*HID + jg);
        float4 Gg = *(const float4*)(G + grow + 2*HID + jg);
        float4 Go = *(const float4*)(G + grow + 3*HID + jg);
        float4 cc = *(const float4*)(c + (size_t)bm*HID + jg);
        const float* cr = Cs + r*EPI_LD;
        float gi[4] = { Gi.x + cr[0*32+jl], Gi.y + cr[0*32+jl+1], Gi.z + cr[0*32+jl+2], Gi.w + cr[0*32+jl+3] };
        float gf[4] = { Gf.x + cr[1*32+jl], Gf.y + cr[1*32+jl+1], Gf.z + cr[1*32+jl+2], Gf.w + cr[1*32+jl+3] };
        float gg[4] = { Gg.x + cr[2*32+jl], Gg.y + cr[2*32+jl+1], Gg.z + cr[2*32+jl+2], Gg.w + cr[2*32+jl+3] };
        float go[4] = { Go.x + cr[3*32+jl], Go.y + cr[3*32+jl+1], Go.z + cr[3*32+jl+2], Go.w + cr[3*32+jl+3] };
        float cold[4] = { cc.x, cc.y, cc.z, cc.w };
        float4 cn, hn;
        float* cnp = &cn.x; float* hnp = &hn.x;
        #pragma unroll
        for (int e = 0; e < 4; e++) {
            const float cv = sigf(gf[e]) * cold[e] + sigf(gi[e]) * tanhf(gg[e]);
            cnp[e] = cv;
            hnp[e] = sigf(go[e]) * tanhf(cv);
        }
        *(float4*)(c + (size_t)bm*HID + jg) = cn;
        store_bf4(hout + (size_t)bm*HID + jg, hn);
        store_bf4(Xout + (size_t)(bm*NVIEW + t)*HID + jg, hn);
    }
}

// ---------------- LSTM pointwise cell (t=0 only: h=c=0) ---------------------
__global__ void __launch_bounds__(256)
lstm_cell0(const float* __restrict__ G, bf16* __restrict__ h,
           float* __restrict__ c, bf16* __restrict__ Xout)
{
    const int idx = blockIdx.x * blockDim.x + threadIdx.x;
    const int r = idx >> 8;
    const int j = idx & 255;

    const float* g = G + (size_t)(r * NVIEW) * (4 * HID);
    const float gi = g[j], gg = g[j + 2*HID], go = g[j + 3*HID];
    const float cn = sigf(gi) * tanhf(gg);
    const float hn = sigf(go) * tanhf(cn);
    c[idx] = cn;
    h[idx] = __float2bfloat16_rn(hn);
    Xout[(size_t)(r * NVIEW) * HID + j] = __float2bfloat16_rn(hn);
}

// ---------------- head ------------------------------------------------------
__global__ void __launch_bounds__(192)
score_kernel(const bf16* __restrict__ X, const float* __restrict__ Wv,
             const float* __restrict__ bv, const float* __restrict__ Ws,
             const float* __restrict__ bs, float* __restrict__ score)
{
    const int bm   = blockIdx.x;
    const int w    = threadIdx.x >> 5;
    const int lane = threadIdx.x & 31;
    __shared__ float sh[NVIEW];

    const bf16* x = X + (size_t)(bm * NVIEW + w) * HID;
    float p = 0.0f;
    #pragma unroll
    for (int k = lane; k < HID; k += 32) p += __bfloat162float(x[k]) * Wv[k];
    #pragma unroll
    for (int o = 16; o; o >>= 1) p += __shfl_xor_sync(0xffffffffu, p, o);
    if (lane == 0) sh[w] = (p + bv[0]) * Ws[w];
    __syncthreads();
    if (threadIdx.x == 0) {
        float s = bs[0];
        #pragma unroll
        for (int n = 0; n < NVIEW; n++) s += sh[n];
        score[bm] = s;
    }
}

__global__ void __launch_bounds__(256)
mean_kernel(const float* __restrict__ score, float* __restrict__ out)
{
    const int b = blockIdx.x;
    const int t = threadIdx.x;
    __shared__ float sh[256];
    sh[t] = score[b * MDIM + t];
    __syncthreads();
    for (int o = 128; o; o >>= 1) { if (t < o) sh[t] += sh[t + o]; __syncthreads(); }
    if (t == 0) out[b] = sh[0] * (1.0f / MDIM);
}

// ---------------- launch ----------------------------------------------------
extern "C" void kernel_launch(void* const* d_in, const int* in_sizes, int n_in,
                              void* d_out, int out_size)
{
    const float* b_x_swin = (const float*)d_in[0];
    const float* b_x_conv = (const float*)d_in[1];
    const float* Wc   = (const float*)d_in[2];
    const float* bc   = (const float*)d_in[3];
    const float* Win  = (const float*)d_in[4];
    const float* b_in = (const float*)d_in[5];
    const float* Wih  = (const float*)d_in[6];
    const float* Whh  = (const float*)d_in[7];
    const float* bih  = (const float*)d_in[8];
    const float* bhh  = (const float*)d_in[9];
    const float* Wv   = (const float*)d_in[10];
    const float* bv   = (const float*)d_in[11];
    const float* Ws   = (const float*)d_in[12];
    const float* bs   = (const float*)d_in[13];
    float* out = (float*)d_out;

    bf16 *bXc, *X1, *X2, *Xa, *Xb, *h, *h2, *bWc, *bWin, *bWih, *bWhh;
    float *G, *c, *score;
    cudaGetSymbolAddress((void**)&bXc, g_bXc);
    cudaGetSymbolAddress((void**)&X1,  g_X1);
    cudaGetSymbolAddress((void**)&X2,  g_X2);
    cudaGetSymbolAddress((void**)&G,   g_G);
    cudaGetSymbolAddress((void**)&Xa,  g_Xa);
    cudaGetSymbolAddress((void**)&Xb,  g_Xb);
    cudaGetSymbolAddress((void**)&h,   g_h);
    cudaGetSymbolAddress((void**)&h2,  g_h2);
    cudaGetSymbolAddress((void**)&c,   g_c);
    cudaGetSymbolAddress((void**)&score, g_score);
    cudaGetSymbolAddress((void**)&bWc,  g_bWc);
    cudaGetSymbolAddress((void**)&bWin, g_bWin);
    cudaGetSymbolAddress((void**)&bWih, g_bWih);
    cudaGetSymbolAddress((void**)&bWhh, g_bWhh);

    cudaFuncSetAttribute(gemm_bf<1,1,1,1>, cudaFuncAttributeMaxDynamicSharedMemorySize, SMEM_SZ);
    cudaFuncSetAttribute(gemm_bf<0,0,1,1>, cudaFuncAttributeMaxDynamicSharedMemorySize, SMEM_SZ);
    cudaFuncSetAttribute(gemm_bf<0,0,2,0>, cudaFuncAttributeMaxDynamicSharedMemorySize, SMEM_SZ);
    cudaFuncSetAttribute(lstm_step,        cudaFuncAttributeMaxDynamicSharedMemorySize, SMEM_SZ);

    // 0) convert inputs/weights to bf16
    f2bf<<<(ROWS*EMBED)/1024, 256>>>(b_x_conv, bXc, ROWS*EMBED);
    f2bf<<<(EMBED*EMBED)/1024, 256>>>(Wc, bWc, EMBED*EMBED);
    f2bf<<<(IN_DIM*EMBED)/1024, 256>>>(Win, bWin, IN_DIM*EMBED);
    f2bf<<<(LAYERS*4*HID*IN_DIM)/1024, 256>>>(Wih, bWih, LAYERS*4*HID*IN_DIM);
    f2bf<<<(LAYERS*4*HID*HID)/1024, 256>>>(Whh, bWhh, LAYERS*4*HID*HID);

    // 1) X1 = b_x_swin + gelu(b_x_conv @ Wc^T + bc)     [49152, 1024] -> bf16
    gemm_bf<1,1,1,1><<<dim3(EMBED/128, ROWS/128), 256, SMEM_SZ>>>(
        bXc, bWc, bc, nullptr, b_x_swin, X1, EMBED, EMBED);

    // 2) X2 = X1 @ Win^T + b_in                         [49152, 256] -> bf16
    gemm_bf<0,0,1,1><<<dim3(IN_DIM/128, ROWS/128), 256, SMEM_SZ>>>(
        X1, bWin, b_in, nullptr, nullptr, X2, IN_DIM, EMBED);

    // 3) LSTM layers
    const bf16* layer_in[LAYERS]  = { X2, Xa, Xb };
    bf16*       layer_out[LAYERS] = { Xa, Xb, Xa };
    bf16* hp[2] = { h, h2 };
    for (int l = 0; l < LAYERS; l++) {
        const bf16*  bWih_l = bWih + (size_t)l * 4 * HID * IN_DIM;
        const bf16*  bWhh_l = bWhh + (size_t)l * 4 * HID * HID;
        const float* bih_l  = bih + (size_t)l * 4 * HID;
        const float* bhh_l  = bhh + (size_t)l * 4 * HID;

        // G = Xin @ Wih^T + bih + bhh                   [49152, 1024] -> fp32
        gemm_bf<0,0,2,0><<<dim3(4*HID/128, ROWS/128), 256, SMEM_SZ>>>(
            layer_in[l], bWih_l, bih_l, bhh_l, nullptr, G, 4*HID, IN_DIM);

        // t = 0: h = c = 0 -> pointwise only
        lstm_cell0<<<(BM*HID)/256, 256>>>(G, hp[0], c, layer_out[l]);

        // t = 1..5: fused GEMM + cell, ping-pong h
        for (int t = 1; t < NVIEW; t++) {
            lstm_step<<<dim3(HID/32, BM/128), 256, SMEM_SZ>>>(
                hp[(t-1) & 1], bWhh_l, G, hp[t & 1], c, layer_out[l], t);
        }
    }

    // 4) head
    score_kernel<<<BM, 192>>>(layer_out[LAYERS-1], Wv, bv, Ws, bs, score);
    mean_kernel<<<BATCH, 256>>>(score, out);
}